// round 1
// baseline (speedup 1.0000x reference)
#include <cuda_runtime.h>
#include <math.h>

// ---------------------------------------------------------------------------
// Problem constants
// ---------------------------------------------------------------------------
#define BATCH 4
#define IMG_H 512
#define IMG_W 512
#define PATCH 64
#define STRIDE_ 32
#define NPATCH 256            // (512/32)^2
#define PATCHES_ELEMS (BATCH * NPATCH * 3 * PATCH * PATCH)   // 12,582,912
#define FLOW_ELEMS    (BATCH * 2 * IMG_H * IMG_W)            //  2,097,152
#define DEF_ELEMS     (BATCH * IMG_H * IMG_W * 2)            //  2,097,152

// Scratch ping-pong buffers (device globals: allocation-free scratch).
// Max activation: [4,32,512,512] = 33,554,432 floats.
__device__ float g_bufA[33554432];
__device__ float g_bufB[33554432];

// ---------------------------------------------------------------------------
// Direct 3x3 conv, pad=1, optional ReLU / tanh.
// Block = 16x16 threads; each thread computes a 2x2 pixel patch for
// COUT_BLK output channels (register blocked). Input streamed through smem
// in CIN_BLK-channel chunks.
// ACT: 0=none, 1=relu, 2=tanh
// ---------------------------------------------------------------------------
template <int CIN, int COUT, int CIN_BLK, int COUT_BLK, int ACT>
__global__ void __launch_bounds__(256)
conv3x3_kernel(const float* __restrict__ in, const float* __restrict__ wgt,
               const float* __restrict__ bias, float* __restrict__ out,
               int H, int W)
{
    constexpr int TILE = 32;
    constexpr int GROUPS = COUT / COUT_BLK;

    const int bx = blockIdx.x * TILE;
    const int by = blockIdx.y * TILE;
    const int cg = blockIdx.z % GROUPS;
    const int b  = blockIdx.z / GROUPS;
    const int co0 = cg * COUT_BLK;

    __shared__ float s_in[CIN_BLK][TILE + 2][TILE + 3];   // +3 pad vs conflicts
    __shared__ float s_w[COUT_BLK][CIN_BLK][9];

    const int tx = threadIdx.x;
    const int ty = threadIdx.y;
    const int tid = ty * 16 + tx;

    float acc[COUT_BLK][2][2];
#pragma unroll
    for (int c = 0; c < COUT_BLK; c++) {
        acc[c][0][0] = 0.f; acc[c][0][1] = 0.f;
        acc[c][1][0] = 0.f; acc[c][1][1] = 0.f;
    }

    for (int ci0 = 0; ci0 < CIN; ci0 += CIN_BLK) {
        __syncthreads();
        // load input chunk (with zero padding)
        constexpr int LOAD_N = CIN_BLK * (TILE + 2) * (TILE + 2);
        for (int idx = tid; idx < LOAD_N; idx += 256) {
            int ci = idx / ((TILE + 2) * (TILE + 2));
            int r  = idx % ((TILE + 2) * (TILE + 2));
            int yy = r / (TILE + 2);
            int xx = r % (TILE + 2);
            int gy = by + yy - 1;
            int gx = bx + xx - 1;
            float v = 0.f;
            if (gy >= 0 && gy < H && gx >= 0 && gx < W)
                v = in[((size_t)(b * CIN + ci0 + ci) * H + gy) * W + gx];
            s_in[ci][yy][xx] = v;
        }
        // load weight chunk
        constexpr int WLOAD_N = COUT_BLK * CIN_BLK * 9;
        for (int idx = tid; idx < WLOAD_N; idx += 256) {
            int co = idx / (CIN_BLK * 9);
            int r  = idx % (CIN_BLK * 9);
            int ci = r / 9;
            int t  = r % 9;
            s_w[co][ci][t] = wgt[((co0 + co) * CIN + ci0 + ci) * 9 + t];
        }
        __syncthreads();

        for (int ci = 0; ci < CIN_BLK; ci++) {
            float iv[4][4];
#pragma unroll
            for (int dy = 0; dy < 4; dy++)
#pragma unroll
                for (int dx = 0; dx < 4; dx++)
                    iv[dy][dx] = s_in[ci][2 * ty + dy][2 * tx + dx];
#pragma unroll
            for (int co = 0; co < COUT_BLK; co++) {
#pragma unroll
                for (int ky = 0; ky < 3; ky++) {
#pragma unroll
                    for (int kx = 0; kx < 3; kx++) {
                        float wv = s_w[co][ci][ky * 3 + kx];
                        acc[co][0][0] = fmaf(iv[ky][kx],       wv, acc[co][0][0]);
                        acc[co][0][1] = fmaf(iv[ky][kx + 1],   wv, acc[co][0][1]);
                        acc[co][1][0] = fmaf(iv[ky + 1][kx],   wv, acc[co][1][0]);
                        acc[co][1][1] = fmaf(iv[ky + 1][kx + 1], wv, acc[co][1][1]);
                    }
                }
            }
        }
    }

#pragma unroll
    for (int co = 0; co < COUT_BLK; co++) {
        float bv = bias[co0 + co];
#pragma unroll
        for (int py = 0; py < 2; py++) {
#pragma unroll
            for (int px = 0; px < 2; px++) {
                float v = acc[co][py][px] + bv;
                if (ACT == 1) v = fmaxf(v, 0.f);
                if (ACT == 2) v = tanhf(v);
                int oy = by + 2 * ty + py;
                int ox = bx + 2 * tx + px;
                out[((size_t)(b * COUT + co0 + co) * H + oy) * W + ox] = v;
            }
        }
    }
}

// ---------------------------------------------------------------------------
// MaxPool 2x2 stride 2
// ---------------------------------------------------------------------------
__global__ void pool2_kernel(const float* __restrict__ in, float* __restrict__ out,
                             int total, int Hout, int Wout)
{
    int idx = blockIdx.x * blockDim.x + threadIdx.x;
    if (idx >= total) return;
    int wo = idx % Wout;
    int ho = (idx / Wout) % Hout;
    int c  = idx / (Wout * Hout);
    int Win = 2 * Wout;
    const float* p = in + ((size_t)c * (2 * Hout) + 2 * ho) * Win + 2 * wo;
    float m0 = fmaxf(p[0], p[1]);
    float m1 = fmaxf(p[Win], p[Win + 1]);
    out[idx] = fmaxf(m0, m1);
}

// ---------------------------------------------------------------------------
// Bilinear upsample x2 (half-pixel, edge clamp == jax.image.resize bilinear)
// ---------------------------------------------------------------------------
__global__ void up2_kernel(const float* __restrict__ in, float* __restrict__ out,
                           int total, int Hin, int Win)
{
    int idx = blockIdx.x * blockDim.x + threadIdx.x;
    if (idx >= total) return;
    int Hout = 2 * Hin, Wout = 2 * Win;
    int ox = idx % Wout;
    int oy = (idx / Wout) % Hout;
    int c  = idx / (Wout * Hout);

    float fy = (oy + 0.5f) * 0.5f - 0.5f;
    float fx = (ox + 0.5f) * 0.5f - 0.5f;
    int y0 = (int)floorf(fy);
    int x0 = (int)floorf(fx);
    float wy = fy - (float)y0;
    float wx = fx - (float)x0;
    int y0c = max(y0, 0), y1c = min(y0 + 1, Hin - 1);
    int x0c = max(x0, 0), x1c = min(x0 + 1, Win - 1);

    const float* base = in + (size_t)c * Hin * Win;
    float v00 = base[y0c * Win + x0c];
    float v01 = base[y0c * Win + x1c];
    float v10 = base[y1c * Win + x0c];
    float v11 = base[y1c * Win + x1c];
    out[idx] = (1.f - wy) * ((1.f - wx) * v00 + wx * v01)
             +        wy  * ((1.f - wx) * v10 + wx * v11);
}

// ---------------------------------------------------------------------------
// deformed = base_grid + flow^T * temp    ([B,H,W,2], x then y)
// ---------------------------------------------------------------------------
__global__ void deform_kernel(const float* __restrict__ flow,
                              const float* __restrict__ temp,
                              float* __restrict__ def)
{
    int idx = blockIdx.x * blockDim.x + threadIdx.x;
    int total = BATCH * IMG_H * IMG_W;
    if (idx >= total) return;
    int w = idx % IMG_W;
    int h = (idx / IMG_W) % IMG_H;
    int b = idx / (IMG_W * IMG_H);
    float gx = -1.0f + 2.0f * (float)w / (float)(IMG_W - 1);
    float gy = -1.0f + 2.0f * (float)h / (float)(IMG_H - 1);
    float t = temp[0];
    float fx = flow[((size_t)(b * 2 + 0) * IMG_H + h) * IMG_W + w];
    float fy = flow[((size_t)(b * 2 + 1) * IMG_H + h) * IMG_W + w];
    def[(size_t)idx * 2 + 0] = gx + fx * t;
    def[(size_t)idx * 2 + 1] = gy + fy * t;
}

// ---------------------------------------------------------------------------
// Patch extraction: grid_sample bilinear, zeros padding, align_corners=False
// out: [B, N=256, C=3, 64, 64]
// ---------------------------------------------------------------------------
__global__ void patches_kernel(const float* __restrict__ x,
                               const float* __restrict__ def,
                               float* __restrict__ out)
{
    int bn = blockIdx.x;            // 0..1023
    int b = bn >> 8;
    int n = bn & 255;
    int hy = n >> 4;
    int wx = n & 15;
    const float* dptr = def + (((size_t)(b * IMG_H + hy * STRIDE_) * IMG_W) + wx * STRIDE_) * 2;
    float cx = dptr[0];
    float cy = dptr[1];

    for (int p = threadIdx.x; p < PATCH * PATCH; p += blockDim.x) {
        int i = p >> 6;
        int j = p & 63;
        float pxv = -1.0f + 2.0f * (float)j / (float)(PATCH - 1);
        float pyv = -1.0f + 2.0f * (float)i / (float)(PATCH - 1);
        float gx = cx + pxv * ((float)PATCH / (float)IMG_W);
        float gy = cy + pyv * ((float)PATCH / (float)IMG_H);
        float ix = ((gx + 1.0f) * (float)IMG_W - 1.0f) * 0.5f;
        float iy = ((gy + 1.0f) * (float)IMG_H - 1.0f) * 0.5f;
        float x0f = floorf(ix), y0f = floorf(iy);
        float wx1 = ix - x0f, wy1 = iy - y0f;
        int x0 = (int)x0f, y0 = (int)y0f;
        int x1 = x0 + 1, y1 = y0 + 1;
        bool vx0 = (x0 >= 0) & (x0 <= IMG_W - 1);
        bool vx1 = (x1 >= 0) & (x1 <= IMG_W - 1);
        bool vy0 = (y0 >= 0) & (y0 <= IMG_H - 1);
        bool vy1 = (y1 >= 0) & (y1 <= IMG_H - 1);
        int x0c = min(max(x0, 0), IMG_W - 1);
        int x1c = min(max(x1, 0), IMG_W - 1);
        int y0c = min(max(y0, 0), IMG_H - 1);
        int y1c = min(max(y1, 0), IMG_H - 1);
        float w00 = (1.f - wx1) * (1.f - wy1) * (float)(vx0 && vy0);
        float w10 = wx1 * (1.f - wy1) * (float)(vx1 && vy0);
        float w01 = (1.f - wx1) * wy1 * (float)(vx0 && vy1);
        float w11 = wx1 * wy1 * (float)(vx1 && vy1);

#pragma unroll
        for (int c = 0; c < 3; c++) {
            const float* img = x + (size_t)(b * 3 + c) * IMG_H * IMG_W;
            float v = img[y0c * IMG_W + x0c] * w00
                    + img[y0c * IMG_W + x1c] * w10
                    + img[y1c * IMG_W + x0c] * w01
                    + img[y1c * IMG_W + x1c] * w11;
            out[((size_t)(bn)*3 + c) * (PATCH * PATCH) + p] = v;
        }
    }
}

// ---------------------------------------------------------------------------
// Launch
// ---------------------------------------------------------------------------
extern "C" void kernel_launch(void* const* d_in, const int* in_sizes, int n_in,
                              void* d_out, int out_size)
{
    const float* x  = (const float*)d_in[0];
    const float* w0 = (const float*)d_in[1];  const float* b0 = (const float*)d_in[2];
    const float* w1 = (const float*)d_in[3];  const float* b1 = (const float*)d_in[4];
    const float* w2 = (const float*)d_in[5];  const float* b2 = (const float*)d_in[6];
    const float* w3 = (const float*)d_in[7];  const float* b3 = (const float*)d_in[8];
    const float* w4 = (const float*)d_in[9];  const float* b4 = (const float*)d_in[10];
    const float* w5 = (const float*)d_in[11]; const float* b5 = (const float*)d_in[12];
    const float* w6 = (const float*)d_in[13]; const float* b6 = (const float*)d_in[14];
    const float* w7 = (const float*)d_in[15]; const float* b7 = (const float*)d_in[16];
    const float* temp = (const float*)d_in[17];

    float* out     = (float*)d_out;
    float* patches = out;                                  // [4,256,3,64,64]
    float* flow    = out + PATCHES_ELEMS;                  // [4,2,512,512]
    float* def     = out + PATCHES_ELEMS + FLOW_ELEMS;     // [4,512,512,2]

    float* A;  cudaGetSymbolAddress((void**)&A, g_bufA);
    float* Bb; cudaGetSymbolAddress((void**)&Bb, g_bufB);

    dim3 blk(16, 16);

    // conv0: 3->32 @512, relu                 (x -> A)
    conv3x3_kernel<3, 32, 3, 16, 1><<<dim3(16, 16, BATCH * 2), blk>>>(x, w0, b0, A, 512, 512);
    // conv1: 32->32 @512, relu                (A -> B)
    conv3x3_kernel<32, 32, 8, 16, 1><<<dim3(16, 16, BATCH * 2), blk>>>(A, w1, b1, Bb, 512, 512);
    // pool: 512->256                          (B -> A)
    {
        int total = BATCH * 32 * 256 * 256;
        pool2_kernel<<<(total + 255) / 256, 256>>>(Bb, A, total, 256, 256);
    }
    // conv2: 32->64 @256, relu                (A -> B)
    conv3x3_kernel<32, 64, 8, 16, 1><<<dim3(8, 8, BATCH * 4), blk>>>(A, w2, b2, Bb, 256, 256);
    // conv3: 64->64 @256, relu                (B -> A)
    conv3x3_kernel<64, 64, 8, 16, 1><<<dim3(8, 8, BATCH * 4), blk>>>(Bb, w3, b3, A, 256, 256);
    // pool: 256->128                          (A -> B)
    {
        int total = BATCH * 64 * 128 * 128;
        pool2_kernel<<<(total + 255) / 256, 256>>>(A, Bb, total, 128, 128);
    }
    // up: 128->256                            (B -> A)
    {
        int total = BATCH * 64 * 256 * 256;
        up2_kernel<<<(total + 255) / 256, 256>>>(Bb, A, total, 128, 128);
    }
    // conv4: 64->64 @256, relu                (A -> B)
    conv3x3_kernel<64, 64, 8, 16, 1><<<dim3(8, 8, BATCH * 4), blk>>>(A, w4, b4, Bb, 256, 256);
    // conv5: 64->32 @256, relu                (B -> A)
    conv3x3_kernel<64, 32, 8, 16, 1><<<dim3(8, 8, BATCH * 2), blk>>>(Bb, w5, b5, A, 256, 256);
    // up: 256->512                            (A -> B)
    {
        int total = BATCH * 32 * 512 * 512;
        up2_kernel<<<(total + 255) / 256, 256>>>(A, Bb, total, 256, 256);
    }
    // conv6: 32->32 @512, relu                (B -> A)
    conv3x3_kernel<32, 32, 8, 16, 1><<<dim3(16, 16, BATCH * 2), blk>>>(Bb, w6, b6, A, 512, 512);
    // conv7: 32->2 @512, tanh                 (A -> flow)
    conv3x3_kernel<32, 2, 8, 2, 2><<<dim3(16, 16, BATCH * 1), blk>>>(A, w7, b7, flow, 512, 512);

    // deformed grid
    {
        int total = BATCH * IMG_H * IMG_W;
        deform_kernel<<<(total + 255) / 256, 256>>>(flow, temp, def);
    }
    // patches
    patches_kernel<<<dim3(BATCH * NPATCH), 256>>>(x, def, patches);
}

// round 2
// speedup vs baseline: 1.1840x; 1.1840x over previous
#include <cuda_runtime.h>
#include <math.h>

// ---------------------------------------------------------------------------
// Problem constants
// ---------------------------------------------------------------------------
#define BATCH 4
#define IMG_H 512
#define IMG_W 512
#define PATCH 64
#define STRIDE_ 32
#define NPATCH 256            // (512/32)^2
#define PATCHES_ELEMS (BATCH * NPATCH * 3 * PATCH * PATCH)   // 12,582,912
#define FLOW_ELEMS    (BATCH * 2 * IMG_H * IMG_W)            //  2,097,152
#define DEF_ELEMS     (BATCH * IMG_H * IMG_W * 2)            //  2,097,152

// Scratch ping-pong buffers (device globals: allocation-free scratch).
__device__ float g_bufA[33554432];
__device__ float g_bufB[33554432];

// ---------------------------------------------------------------------------
// Direct 3x3 conv, pad=1, optional ReLU / tanh.
// Block = 16x16 threads; each thread computes a 2x2 pixel patch for
// COUT_BLK output channels. Input streamed through smem in CIN_BLK chunks.
// COUT_BLK=8 keeps acc at 32 regs -> 3 CTAs/SM (occupancy play).
// ACT: 0=none, 1=relu, 2=tanh
// ---------------------------------------------------------------------------
template <int CIN, int COUT, int CIN_BLK, int COUT_BLK, int ACT>
__global__ void __launch_bounds__(256, 3)
conv3x3_kernel(const float* __restrict__ in, const float* __restrict__ wgt,
               const float* __restrict__ bias, float* __restrict__ out,
               int H, int W)
{
    constexpr int TILE = 32;
    constexpr int GROUPS = COUT / COUT_BLK;

    const int bx = blockIdx.x * TILE;
    const int by = blockIdx.y * TILE;
    const int cg = blockIdx.z % GROUPS;
    const int b  = blockIdx.z / GROUPS;
    const int co0 = cg * COUT_BLK;

    __shared__ float s_in[CIN_BLK][TILE + 2][TILE + 3];   // +3 pad vs conflicts
    __shared__ float s_w[CIN_BLK][COUT_BLK][9];

    const int tx = threadIdx.x;
    const int ty = threadIdx.y;
    const int tid = ty * 16 + tx;

    float acc[COUT_BLK][2][2];
#pragma unroll
    for (int c = 0; c < COUT_BLK; c++) {
        acc[c][0][0] = 0.f; acc[c][0][1] = 0.f;
        acc[c][1][0] = 0.f; acc[c][1][1] = 0.f;
    }

    for (int ci0 = 0; ci0 < CIN; ci0 += CIN_BLK) {
        __syncthreads();
        // load input chunk (with zero padding)
        constexpr int LOAD_N = CIN_BLK * (TILE + 2) * (TILE + 2);
#pragma unroll 4
        for (int idx = tid; idx < LOAD_N; idx += 256) {
            int ci = idx / ((TILE + 2) * (TILE + 2));
            int r  = idx % ((TILE + 2) * (TILE + 2));
            int yy = r / (TILE + 2);
            int xx = r % (TILE + 2);
            int gy = by + yy - 1;
            int gx = bx + xx - 1;
            float v = 0.f;
            if (gy >= 0 && gy < H && gx >= 0 && gx < W)
                v = in[((size_t)(b * CIN + ci0 + ci) * H + gy) * W + gx];
            s_in[ci][yy][xx] = v;
        }
        // load weight chunk (ci-major so inner loop walks contiguously)
        constexpr int WLOAD_N = COUT_BLK * CIN_BLK * 9;
        for (int idx = tid; idx < WLOAD_N; idx += 256) {
            int co = idx / (CIN_BLK * 9);
            int r  = idx % (CIN_BLK * 9);
            int ci = r / 9;
            int t  = r % 9;
            s_w[ci][co][t] = wgt[((co0 + co) * CIN + ci0 + ci) * 9 + t];
        }
        __syncthreads();

#pragma unroll 1
        for (int ci = 0; ci < CIN_BLK; ci++) {
            float iv[4][4];
#pragma unroll
            for (int dy = 0; dy < 4; dy++)
#pragma unroll
                for (int dx = 0; dx < 4; dx++)
                    iv[dy][dx] = s_in[ci][2 * ty + dy][2 * tx + dx];
#pragma unroll
            for (int co = 0; co < COUT_BLK; co++) {
#pragma unroll
                for (int ky = 0; ky < 3; ky++) {
#pragma unroll
                    for (int kx = 0; kx < 3; kx++) {
                        float wv = s_w[ci][co][ky * 3 + kx];
                        acc[co][0][0] = fmaf(iv[ky][kx],         wv, acc[co][0][0]);
                        acc[co][0][1] = fmaf(iv[ky][kx + 1],     wv, acc[co][0][1]);
                        acc[co][1][0] = fmaf(iv[ky + 1][kx],     wv, acc[co][1][0]);
                        acc[co][1][1] = fmaf(iv[ky + 1][kx + 1], wv, acc[co][1][1]);
                    }
                }
            }
        }
    }

#pragma unroll
    for (int co = 0; co < COUT_BLK; co++) {
        float bv = bias[co0 + co];
#pragma unroll
        for (int py = 0; py < 2; py++) {
            float v0 = acc[co][py][0] + bv;
            float v1 = acc[co][py][1] + bv;
            if (ACT == 1) { v0 = fmaxf(v0, 0.f); v1 = fmaxf(v1, 0.f); }
            if (ACT == 2) { v0 = tanhf(v0); v1 = tanhf(v1); }
            int oy = by + 2 * ty + py;
            int ox = bx + 2 * tx;
            float2 pv = make_float2(v0, v1);
            *(float2*)&out[((size_t)(b * COUT + co0 + co) * H + oy) * W + ox] = pv;
        }
    }
}

// ---------------------------------------------------------------------------
// MaxPool 2x2 stride 2
// ---------------------------------------------------------------------------
__global__ void pool2_kernel(const float* __restrict__ in, float* __restrict__ out,
                             int total, int Hout, int Wout)
{
    int idx = blockIdx.x * blockDim.x + threadIdx.x;
    if (idx >= total) return;
    int wo = idx % Wout;
    int ho = (idx / Wout) % Hout;
    int c  = idx / (Wout * Hout);
    int Win = 2 * Wout;
    const float* p = in + ((size_t)c * (2 * Hout) + 2 * ho) * Win + 2 * wo;
    float m0 = fmaxf(p[0], p[1]);
    float m1 = fmaxf(p[Win], p[Win + 1]);
    out[idx] = fmaxf(m0, m1);
}

// ---------------------------------------------------------------------------
// Bilinear upsample x2 (half-pixel, edge clamp == jax.image.resize bilinear)
// ---------------------------------------------------------------------------
__global__ void up2_kernel(const float* __restrict__ in, float* __restrict__ out,
                           int total, int Hin, int Win)
{
    int idx = blockIdx.x * blockDim.x + threadIdx.x;
    if (idx >= total) return;
    int Hout = 2 * Hin, Wout = 2 * Win;
    int ox = idx % Wout;
    int oy = (idx / Wout) % Hout;
    int c  = idx / (Wout * Hout);

    float fy = (oy + 0.5f) * 0.5f - 0.5f;
    float fx = (ox + 0.5f) * 0.5f - 0.5f;
    int y0 = (int)floorf(fy);
    int x0 = (int)floorf(fx);
    float wy = fy - (float)y0;
    float wx = fx - (float)x0;
    int y0c = max(y0, 0), y1c = min(y0 + 1, Hin - 1);
    int x0c = max(x0, 0), x1c = min(x0 + 1, Win - 1);

    const float* base = in + (size_t)c * Hin * Win;
    float v00 = base[y0c * Win + x0c];
    float v01 = base[y0c * Win + x1c];
    float v10 = base[y1c * Win + x0c];
    float v11 = base[y1c * Win + x1c];
    out[idx] = (1.f - wy) * ((1.f - wx) * v00 + wx * v01)
             +        wy  * ((1.f - wx) * v10 + wx * v11);
}

// ---------------------------------------------------------------------------
// deformed = base_grid + flow^T * temp    ([B,H,W,2], x then y)
// ---------------------------------------------------------------------------
__global__ void deform_kernel(const float* __restrict__ flow,
                              const float* __restrict__ temp,
                              float* __restrict__ def)
{
    int idx = blockIdx.x * blockDim.x + threadIdx.x;
    int total = BATCH * IMG_H * IMG_W;
    if (idx >= total) return;
    int w = idx % IMG_W;
    int h = (idx / IMG_W) % IMG_H;
    int b = idx / (IMG_W * IMG_H);
    float gx = -1.0f + 2.0f * (float)w / (float)(IMG_W - 1);
    float gy = -1.0f + 2.0f * (float)h / (float)(IMG_H - 1);
    float t = temp[0];
    float fx = flow[((size_t)(b * 2 + 0) * IMG_H + h) * IMG_W + w];
    float fy = flow[((size_t)(b * 2 + 1) * IMG_H + h) * IMG_W + w];
    def[(size_t)idx * 2 + 0] = gx + fx * t;
    def[(size_t)idx * 2 + 1] = gy + fy * t;
}

// ---------------------------------------------------------------------------
// Patch extraction: grid_sample bilinear, zeros padding, align_corners=False
// out: [B, N=256, C=3, 64, 64]
// ---------------------------------------------------------------------------
__global__ void patches_kernel(const float* __restrict__ x,
                               const float* __restrict__ def,
                               float* __restrict__ out)
{
    int bn = blockIdx.x;            // 0..1023
    int b = bn >> 8;
    int n = bn & 255;
    int hy = n >> 4;
    int wx = n & 15;
    const float* dptr = def + (((size_t)(b * IMG_H + hy * STRIDE_) * IMG_W) + wx * STRIDE_) * 2;
    float cx = dptr[0];
    float cy = dptr[1];

    for (int p = threadIdx.x; p < PATCH * PATCH; p += blockDim.x) {
        int i = p >> 6;
        int j = p & 63;
        float pxv = -1.0f + 2.0f * (float)j / (float)(PATCH - 1);
        float pyv = -1.0f + 2.0f * (float)i / (float)(PATCH - 1);
        float gx = cx + pxv * ((float)PATCH / (float)IMG_W);
        float gy = cy + pyv * ((float)PATCH / (float)IMG_H);
        float ix = ((gx + 1.0f) * (float)IMG_W - 1.0f) * 0.5f;
        float iy = ((gy + 1.0f) * (float)IMG_H - 1.0f) * 0.5f;
        float x0f = floorf(ix), y0f = floorf(iy);
        float wx1 = ix - x0f, wy1 = iy - y0f;
        int x0 = (int)x0f, y0 = (int)y0f;
        int x1 = x0 + 1, y1 = y0 + 1;
        bool vx0 = (x0 >= 0) & (x0 <= IMG_W - 1);
        bool vx1 = (x1 >= 0) & (x1 <= IMG_W - 1);
        bool vy0 = (y0 >= 0) & (y0 <= IMG_H - 1);
        bool vy1 = (y1 >= 0) & (y1 <= IMG_H - 1);
        int x0c = min(max(x0, 0), IMG_W - 1);
        int x1c = min(max(x1, 0), IMG_W - 1);
        int y0c = min(max(y0, 0), IMG_H - 1);
        int y1c = min(max(y1, 0), IMG_H - 1);
        float w00 = (1.f - wx1) * (1.f - wy1) * (float)(vx0 && vy0);
        float w10 = wx1 * (1.f - wy1) * (float)(vx1 && vy0);
        float w01 = (1.f - wx1) * wy1 * (float)(vx0 && vy1);
        float w11 = wx1 * wy1 * (float)(vx1 && vy1);

#pragma unroll
        for (int c = 0; c < 3; c++) {
            const float* img = x + (size_t)(b * 3 + c) * IMG_H * IMG_W;
            float v = img[y0c * IMG_W + x0c] * w00
                    + img[y0c * IMG_W + x1c] * w10
                    + img[y1c * IMG_W + x0c] * w01
                    + img[y1c * IMG_W + x1c] * w11;
            out[((size_t)(bn)*3 + c) * (PATCH * PATCH) + p] = v;
        }
    }
}

// ---------------------------------------------------------------------------
// Launch
// ---------------------------------------------------------------------------
extern "C" void kernel_launch(void* const* d_in, const int* in_sizes, int n_in,
                              void* d_out, int out_size)
{
    const float* x  = (const float*)d_in[0];
    const float* w0 = (const float*)d_in[1];  const float* b0 = (const float*)d_in[2];
    const float* w1 = (const float*)d_in[3];  const float* b1 = (const float*)d_in[4];
    const float* w2 = (const float*)d_in[5];  const float* b2 = (const float*)d_in[6];
    const float* w3 = (const float*)d_in[7];  const float* b3 = (const float*)d_in[8];
    const float* w4 = (const float*)d_in[9];  const float* b4 = (const float*)d_in[10];
    const float* w5 = (const float*)d_in[11]; const float* b5 = (const float*)d_in[12];
    const float* w6 = (const float*)d_in[13]; const float* b6 = (const float*)d_in[14];
    const float* w7 = (const float*)d_in[15]; const float* b7 = (const float*)d_in[16];
    const float* temp = (const float*)d_in[17];

    float* out     = (float*)d_out;
    float* patches = out;                                  // [4,256,3,64,64]
    float* flow    = out + PATCHES_ELEMS;                  // [4,2,512,512]
    float* def     = out + PATCHES_ELEMS + FLOW_ELEMS;     // [4,512,512,2]

    float* A;  cudaGetSymbolAddress((void**)&A, g_bufA);
    float* Bb; cudaGetSymbolAddress((void**)&Bb, g_bufB);

    dim3 blk(16, 16);

    // conv0: 3->32 @512, relu                 (x -> A)   groups=4
    conv3x3_kernel<3, 32, 3, 8, 1><<<dim3(16, 16, BATCH * 4), blk>>>(x, w0, b0, A, 512, 512);
    // conv1: 32->32 @512, relu                (A -> B)   groups=4
    conv3x3_kernel<32, 32, 8, 8, 1><<<dim3(16, 16, BATCH * 4), blk>>>(A, w1, b1, Bb, 512, 512);
    // pool: 512->256                          (B -> A)
    {
        int total = BATCH * 32 * 256 * 256;
        pool2_kernel<<<(total + 255) / 256, 256>>>(Bb, A, total, 256, 256);
    }
    // conv2: 32->64 @256, relu                (A -> B)   groups=8
    conv3x3_kernel<32, 64, 8, 8, 1><<<dim3(8, 8, BATCH * 8), blk>>>(A, w2, b2, Bb, 256, 256);
    // conv3: 64->64 @256, relu                (B -> A)   groups=8
    conv3x3_kernel<64, 64, 8, 8, 1><<<dim3(8, 8, BATCH * 8), blk>>>(Bb, w3, b3, A, 256, 256);
    // pool: 256->128                          (A -> B)
    {
        int total = BATCH * 64 * 128 * 128;
        pool2_kernel<<<(total + 255) / 256, 256>>>(A, Bb, total, 128, 128);
    }
    // up: 128->256                            (B -> A)
    {
        int total = BATCH * 64 * 256 * 256;
        up2_kernel<<<(total + 255) / 256, 256>>>(Bb, A, total, 128, 128);
    }
    // conv4: 64->64 @256, relu                (A -> B)   groups=8
    conv3x3_kernel<64, 64, 8, 8, 1><<<dim3(8, 8, BATCH * 8), blk>>>(A, w4, b4, Bb, 256, 256);
    // conv5: 64->32 @256, relu                (B -> A)   groups=4
    conv3x3_kernel<64, 32, 8, 8, 1><<<dim3(8, 8, BATCH * 4), blk>>>(Bb, w5, b5, A, 256, 256);
    // up: 256->512                            (A -> B)
    {
        int total = BATCH * 32 * 512 * 512;
        up2_kernel<<<(total + 255) / 256, 256>>>(A, Bb, total, 256, 256);
    }
    // conv6: 32->32 @512, relu                (B -> A)   groups=4
    conv3x3_kernel<32, 32, 8, 8, 1><<<dim3(16, 16, BATCH * 4), blk>>>(Bb, w6, b6, A, 512, 512);
    // conv7: 32->2 @512, tanh                 (A -> flow) groups=1
    conv3x3_kernel<32, 2, 8, 2, 2><<<dim3(16, 16, BATCH * 1), blk>>>(A, w7, b7, flow, 512, 512);

    // deformed grid
    {
        int total = BATCH * IMG_H * IMG_W;
        deform_kernel<<<(total + 255) / 256, 256>>>(flow, temp, def);
    }
    // patches
    patches_kernel<<<dim3(BATCH * NPATCH), 256>>>(x, def, patches);
}